// round 1
// baseline (speedup 1.0000x reference)
#include <cuda_runtime.h>
#include <math.h>

// Problem constants: [T,B,H,N,D] = [2,2,16,1024,64] -> BH = 64 fused batch-heads
#define BH 64
#define NSEQ 1024
#define DIM 64
#define NROWS (BH * NSEQ)            // 65536
#define CTX_ELEMS (BH * NSEQ * DIM)  // 4194304
#define SC_ELEMS  (BH * NSEQ * NSEQ) // 67108864

// Softmax row statistics scratch (no cudaMalloc allowed -> device globals)
__device__ float g_rmax[NROWS];
__device__ float g_rinv[NROWS];

// ---------------------------------------------------------------------------
// Kernel 1: scores[bh,i,j] = (1/8) * sum_d q[bh,i,d] * k[bh,j,d]
// 64x64 tile per block, 256 threads, 4x4 register microtile per thread.
// ---------------------------------------------------------------------------
__global__ __launch_bounds__(256)
void scores_kernel(const float* __restrict__ q,
                   const float* __restrict__ k,
                   float* __restrict__ scores)
{
    const int bh = blockIdx.z;
    const int i0 = blockIdx.x * 64;
    const int j0 = blockIdx.y * 64;

    __shared__ float qs[64][68];   // qs[d][i]  (transposed, padded: 68*4B stride keeps 16B align)
    __shared__ float ks[64][68];   // ks[d][j]

    const float* qb = q + (size_t)bh * NSEQ * DIM + (size_t)i0 * DIM;
    const float* kb = k + (size_t)bh * NSEQ * DIM + (size_t)j0 * DIM;

    const int t = threadIdx.x;
    #pragma unroll
    for (int c = 0; c < 16; ++c) {           // 256 threads * 16 = 4096 elems each tile
        int idx = c * 256 + t;
        int row = idx >> 6;
        int d   = idx & 63;
        qs[d][row] = qb[idx];
        ks[d][row] = kb[idx];
    }
    __syncthreads();

    const int ty = t >> 4;     // 0..15 -> query sub-row group
    const int tx = t & 15;     // 0..15 -> key sub-col group

    float acc[4][4];
    #pragma unroll
    for (int a = 0; a < 4; ++a)
        #pragma unroll
        for (int b = 0; b < 4; ++b) acc[a][b] = 0.f;

    #pragma unroll 16
    for (int d = 0; d < 64; ++d) {
        const float4 av = *reinterpret_cast<const float4*>(&qs[d][ty << 2]);
        const float4 bv = *reinterpret_cast<const float4*>(&ks[d][tx << 2]);
        const float a[4] = {av.x, av.y, av.z, av.w};
        const float b[4] = {bv.x, bv.y, bv.z, bv.w};
        #pragma unroll
        for (int r = 0; r < 4; ++r)
            #pragma unroll
            for (int c = 0; c < 4; ++c)
                acc[r][c] = fmaf(a[r], b[c], acc[r][c]);
    }

    const float scale = 0.125f;  // 1/sqrt(64)
    float* sb = scores + (size_t)bh * NSEQ * NSEQ;
    #pragma unroll
    for (int r = 0; r < 4; ++r) {
        int gi = i0 + (ty << 2) + r;
        float4 o;
        o.x = acc[r][0] * scale;
        o.y = acc[r][1] * scale;
        o.z = acc[r][2] * scale;
        o.w = acc[r][3] * scale;
        *reinterpret_cast<float4*>(&sb[(size_t)gi * NSEQ + j0 + (tx << 2)]) = o;
    }
}

// ---------------------------------------------------------------------------
// Kernel 2: per-row softmax stats. One warp per row (8 rows / block).
// ---------------------------------------------------------------------------
__global__ __launch_bounds__(256)
void stats_kernel(const float* __restrict__ scores)
{
    const int row  = blockIdx.x * 8 + (threadIdx.x >> 5);
    const int lane = threadIdx.x & 31;
    const float4* p = reinterpret_cast<const float4*>(scores + (size_t)row * NSEQ);

    float4 vals[8];
    float m = -INFINITY;
    #pragma unroll
    for (int c = 0; c < 8; ++c) {
        float4 v = p[c * 32 + lane];
        vals[c] = v;
        m = fmaxf(m, fmaxf(fmaxf(v.x, v.y), fmaxf(v.z, v.w)));
    }
    #pragma unroll
    for (int o = 16; o > 0; o >>= 1)
        m = fmaxf(m, __shfl_xor_sync(0xffffffffu, m, o));

    float s = 0.f;
    #pragma unroll
    for (int c = 0; c < 8; ++c) {
        float4 v = vals[c];
        s += __expf(v.x - m) + __expf(v.y - m) + __expf(v.z - m) + __expf(v.w - m);
    }
    #pragma unroll
    for (int o = 16; o > 0; o >>= 1)
        s += __shfl_xor_sync(0xffffffffu, s, o);

    if (lane == 0) {
        g_rmax[row] = m;
        g_rinv[row] = 1.f / s;
    }
}

// ---------------------------------------------------------------------------
// Kernel 3: attn = exp(scores - m) * inv ; write attn ; context = attn @ V.
// One block per (bh, 64-row query tile). 256 threads, 4x4 microtile.
// ---------------------------------------------------------------------------
__global__ __launch_bounds__(256)
void av_kernel(const float* __restrict__ scores,
               const float* __restrict__ v,
               float* __restrict__ attn,
               float* __restrict__ ctx)
{
    const int bh = blockIdx.y;
    const int i0 = blockIdx.x * 64;

    __shared__ float ps[64][68];   // ps[j][i]  attn tile, transposed
    __shared__ float vs[64][68];   // vs[j][d]

    const int t  = threadIdx.x;
    const int ty = t >> 4;
    const int tx = t & 15;

    // Per-row stats for the 4 query rows this thread's loads touch (row = c*16 + ty)
    const int rowbase = bh * NSEQ + i0;

    float acc[4][4];
    #pragma unroll
    for (int a = 0; a < 4; ++a)
        #pragma unroll
        for (int b = 0; b < 4; ++b) acc[a][b] = 0.f;

    const float* sb = scores + (size_t)bh * NSEQ * NSEQ + (size_t)i0 * NSEQ;
    float*       ab = attn   + (size_t)bh * NSEQ * NSEQ + (size_t)i0 * NSEQ;
    const float* vb = v      + (size_t)bh * NSEQ * DIM;

    for (int kt = 0; kt < NSEQ / 64; ++kt) {
        const int j0 = kt * 64;
        __syncthreads();   // protect prior iteration's smem reads

        // Load scores tile -> compute attn -> write attn + stage transposed in smem
        #pragma unroll
        for (int c = 0; c < 4; ++c) {
            int idx = c * 1024 + t * 4;          // row = c*16+ty, col = tx*4
            int row = c * 16 + ty;
            int col = tx << 2;
            float m   = g_rmax[rowbase + row];
            float inv = g_rinv[rowbase + row];
            float4 s = *reinterpret_cast<const float4*>(&sb[(size_t)row * NSEQ + j0 + col]);
            float4 pv;
            pv.x = __expf(s.x - m) * inv;
            pv.y = __expf(s.y - m) * inv;
            pv.z = __expf(s.z - m) * inv;
            pv.w = __expf(s.w - m) * inv;
            *reinterpret_cast<float4*>(&ab[(size_t)row * NSEQ + j0 + col]) = pv;
            ps[col + 0][row] = pv.x;
            ps[col + 1][row] = pv.y;
            ps[col + 2][row] = pv.z;
            ps[col + 3][row] = pv.w;
            // V tile: same index pattern, direct layout
            float4 vv = *reinterpret_cast<const float4*>(&vb[(size_t)(j0 + row) * DIM + col]);
            *reinterpret_cast<float4*>(&vs[row][col]) = vv;
            (void)idx;
        }
        __syncthreads();

        #pragma unroll 16
        for (int j = 0; j < 64; ++j) {
            const float4 pv = *reinterpret_cast<const float4*>(&ps[j][ty << 2]);
            const float4 vv = *reinterpret_cast<const float4*>(&vs[j][tx << 2]);
            const float a[4] = {pv.x, pv.y, pv.z, pv.w};
            const float b[4] = {vv.x, vv.y, vv.z, vv.w};
            #pragma unroll
            for (int r = 0; r < 4; ++r)
                #pragma unroll
                for (int c = 0; c < 4; ++c)
                    acc[r][c] = fmaf(a[r], b[c], acc[r][c]);
        }
    }

    float* cb = ctx + (size_t)bh * NSEQ * DIM + (size_t)i0 * DIM;
    #pragma unroll
    for (int r = 0; r < 4; ++r) {
        int gi = (ty << 2) + r;
        float4 o;
        o.x = acc[r][0];
        o.y = acc[r][1];
        o.z = acc[r][2];
        o.w = acc[r][3];
        *reinterpret_cast<float4*>(&cb[(size_t)gi * DIM + (tx << 2)]) = o;
    }
}

// ---------------------------------------------------------------------------
extern "C" void kernel_launch(void* const* d_in, const int* in_sizes, int n_in,
                              void* d_out, int out_size)
{
    const float* q = (const float*)d_in[0];
    const float* k = (const float*)d_in[1];
    const float* v = (const float*)d_in[2];

    float* out    = (float*)d_out;
    float* ctx    = out;                       // [T,B,H,N,D]
    float* scores = out + CTX_ELEMS;           // [T,B,H,N,N]
    float* attn   = scores + SC_ELEMS;         // [T,B,H,N,N]

    dim3 g1(NSEQ / 64, NSEQ / 64, BH);
    scores_kernel<<<g1, 256>>>(q, k, scores);

    stats_kernel<<<NROWS / 8, 256>>>(scores);

    dim3 g3(NSEQ / 64, BH);
    av_kernel<<<g3, 256>>>(scores, v, attn, ctx);
}

// round 6
// speedup vs baseline: 1.1011x; 1.1011x over previous
#include <cuda_runtime.h>
#include <cuda_bf16.h>
#include <cstdint>
#include <math.h>

#define BHN 64
#define NS  1024
#define DD  64

// softmax row stats (no cudaMalloc allowed -> device globals)
__device__ float g_rmax[BHN * NS];
__device__ float g_rinv[BHN * NS];

// ---------------- helpers ----------------
__device__ __forceinline__ uint32_t smem_u32(const void* p) {
    uint32_t a;
    asm("{ .reg .u64 t; cvta.to.shared.u64 t, %1; cvt.u32.u64 %0, t; }" : "=r"(a) : "l"(p));
    return a;
}
// split two floats into bf16 hi/lo packed pairs
__device__ __forceinline__ void split2(float a, float b, uint32_t& hi, uint32_t& lo) {
    __nv_bfloat16 ha = __float2bfloat16_rn(a), hb = __float2bfloat16_rn(b);
    float ra = a - __bfloat162float(ha);
    float rb = b - __bfloat162float(hb);
    __nv_bfloat162 H; H.x = ha; H.y = hb;
    __nv_bfloat162 L; L.x = __float2bfloat16_rn(ra); L.y = __float2bfloat16_rn(rb);
    hi = *reinterpret_cast<uint32_t*>(&H);
    lo = *reinterpret_cast<uint32_t*>(&L);
}

// 64-half rows (128B), 8 chunks of 16B, XOR-swizzled by row%8
__device__ __forceinline__ uint32_t off64(int row, int halfcol) {
    return (uint32_t)((row << 7) + ((((halfcol >> 3) ^ (row & 7)) << 4) | ((halfcol & 7) << 1)));
}
// 128-half rows (256B), 16 chunks of 16B, XOR-swizzled (low 3 chunk bits)
__device__ __forceinline__ uint32_t off128(int row, int halfcol) {
    return (uint32_t)((row << 8) + ((((halfcol >> 3) ^ (row & 7)) << 4) | ((halfcol & 7) << 1)));
}

__device__ __forceinline__ void ldsm4(uint32_t (&r)[4], uint32_t addr) {
    asm volatile("ldmatrix.sync.aligned.m8n8.x4.shared.b16 {%0,%1,%2,%3}, [%4];"
                 : "=r"(r[0]), "=r"(r[1]), "=r"(r[2]), "=r"(r[3]) : "r"(addr));
}
__device__ __forceinline__ void ldsm4t(uint32_t (&r)[4], uint32_t addr) {
    asm volatile("ldmatrix.sync.aligned.m8n8.x4.trans.shared.b16 {%0,%1,%2,%3}, [%4];"
                 : "=r"(r[0]), "=r"(r[1]), "=r"(r[2]), "=r"(r[3]) : "r"(addr));
}
__device__ __forceinline__ void mma16816(float* c, const uint32_t (&a)[4], uint32_t b0, uint32_t b1) {
    asm volatile(
        "mma.sync.aligned.m16n8k16.row.col.f32.bf16.bf16.f32 "
        "{%0,%1,%2,%3}, {%4,%5,%6,%7}, {%8,%9}, {%0,%1,%2,%3};"
        : "+f"(c[0]), "+f"(c[1]), "+f"(c[2]), "+f"(c[3])
        : "r"(a[0]), "r"(a[1]), "r"(a[2]), "r"(a[3]), "r"(b0), "r"(b1));
}

// load a 128x64 f32 tile, split to bf16 hi/lo, store swizzled (256 threads)
__device__ __forceinline__ void load_split64(const float* __restrict__ g,
                                             char* smH, char* smL, int t) {
    const float4* p = (const float4*)g;
    #pragma unroll
    for (int c = 0; c < 8; ++c) {
        int idx = (c << 8) + t;            // 2048 float4
        float4 x = p[idx];
        int row = idx >> 4, d0 = (idx & 15) << 2;
        uint32_t h0, l0, h1, l1;
        split2(x.x, x.y, h0, l0);
        split2(x.z, x.w, h1, l1);
        uint32_t o = off64(row, d0);
        *reinterpret_cast<uint2*>(smH + o) = make_uint2(h0, h1);
        *reinterpret_cast<uint2*>(smL + o) = make_uint2(l0, l1);
    }
}

#define K1_SMEM (65536 + 2048 + 1024)
#define K2_SMEM (98304 + 1024 + 1024)

// ---------------------------------------------------------------------------
// Kernel 1: scores = (Q K^T)/8 via mma.sync bf16 3-pass; online softmax stats
// fused. Block: 256 thr (8 warps, 4x2 MxN), tile 128x128 per j-step.
// ---------------------------------------------------------------------------
__global__ void __launch_bounds__(256, 1)
k1_scores(const float* __restrict__ qg, const float* __restrict__ kg,
          float* __restrict__ scores)
{
    extern __shared__ char dsm_raw[];
    char* smb = (char*)(((uintptr_t)dsm_raw + 1023) & ~(uintptr_t)1023);

    const int t = threadIdx.x, lane = t & 31, wid = t >> 5;
    const int wm = wid >> 1, wn = wid & 1;
    const int bh = blockIdx.y, i0 = blockIdx.x << 7;

    char* sQH = smb;
    char* sQL = smb + 16384;
    char* sKH = smb + 32768;
    char* sKL = smb + 49152;
    float* sm_m = (float*)(smb + 65536);   // [2][128]
    float* sm_s = (float*)(smb + 66560);   // [2][128]

    const uint32_t uQH = smem_u32(sQH), uQL = smem_u32(sQL);
    const uint32_t uKH = smem_u32(sKH), uKL = smem_u32(sKL);

    load_split64(qg + ((size_t)bh * NS + i0) * DD, sQH, sQL, t);

    float m_run[4], s_run[4];
    #pragma unroll
    for (int s = 0; s < 4; ++s) { m_run[s] = -INFINITY; s_run[s] = 0.f; }

    const int arow = wm * 32 + (lane & 15);
    const int lq = lane >> 2, lr = lane & 3;

    for (int jt = 0; jt < 8; ++jt) {
        const int j0 = jt << 7;
        load_split64(kg + ((size_t)bh * NS + j0) * DD, sKH, sKL, t);
        __syncthreads();

        float acc[2][8][4];
        #pragma unroll
        for (int mb = 0; mb < 2; ++mb)
            #pragma unroll
            for (int nt = 0; nt < 8; ++nt)
                #pragma unroll
                for (int e = 0; e < 4; ++e) acc[mb][nt][e] = 0.f;

        #pragma unroll
        for (int ks = 0; ks < 4; ++ks) {
            const int kc = ks * 16 + ((lane >> 4) << 3);
            uint32_t aH[2][4], aL[2][4];
            #pragma unroll
            for (int mb = 0; mb < 2; ++mb) {
                uint32_t o = off64(arow + mb * 16, kc);
                ldsm4(aH[mb], uQH + o);
                ldsm4(aL[mb], uQL + o);
            }
            #pragma unroll
            for (int g = 0; g < 4; ++g) {
                uint32_t bo = off64(wn * 64 + g * 16 + (lane & 15), kc);
                uint32_t bH[4], bL[4];
                ldsm4(bH, uKH + bo);
                ldsm4(bL, uKL + bo);
                #pragma unroll
                for (int mb = 0; mb < 2; ++mb) {
                    // n-tile 2g : frag (r0, r2); n-tile 2g+1 : frag (r1, r3)
                    mma16816(acc[mb][2 * g],     aH[mb], bH[0], bH[2]);
                    mma16816(acc[mb][2 * g + 1], aH[mb], bH[1], bH[3]);
                    mma16816(acc[mb][2 * g],     aH[mb], bL[0], bL[2]);
                    mma16816(acc[mb][2 * g + 1], aH[mb], bL[1], bL[3]);
                    mma16816(acc[mb][2 * g],     aL[mb], bH[0], bH[2]);
                    mma16816(acc[mb][2 * g + 1], aL[mb], bH[1], bH[3]);
                }
            }
        }

        // epilogue: scale, online stats, write scores
        #pragma unroll
        for (int mb = 0; mb < 2; ++mb) {
            #pragma unroll
            for (int sl = 0; sl < 2; ++sl) {
                float v[16];
                float cm = -INFINITY;
                #pragma unroll
                for (int nt = 0; nt < 8; ++nt) {
                    v[2 * nt]     = acc[mb][nt][sl * 2]     * 0.125f;
                    v[2 * nt + 1] = acc[mb][nt][sl * 2 + 1] * 0.125f;
                    cm = fmaxf(cm, fmaxf(v[2 * nt], v[2 * nt + 1]));
                }
                const int slot = mb * 2 + sl;
                float nm = fmaxf(m_run[slot], cm);
                float a = 0.f;
                #pragma unroll
                for (int e = 0; e < 16; ++e) a += __expf(v[e] - nm);
                s_run[slot] = s_run[slot] * __expf(m_run[slot] - nm) + a;
                m_run[slot] = nm;

                const int grow = i0 + wm * 32 + mb * 16 + sl * 8 + lq;
                float* sp = scores + ((size_t)bh << 20) + (size_t)grow * NS
                            + j0 + wn * 64 + lr * 2;
                #pragma unroll
                for (int nt = 0; nt < 8; ++nt) {
                    float2 o; o.x = v[2 * nt]; o.y = v[2 * nt + 1];
                    *reinterpret_cast<float2*>(sp + nt * 8) = o;
                }
            }
        }
        __syncthreads();
    }

    // lane-quad reduce (m,s) then cross-warp(N) combine
    #pragma unroll
    for (int slot = 0; slot < 4; ++slot) {
        float m = m_run[slot], s = s_run[slot];
        #pragma unroll
        for (int o = 1; o <= 2; o <<= 1) {
            float mo = __shfl_xor_sync(0xffffffffu, m, o);
            float so = __shfl_xor_sync(0xffffffffu, s, o);
            float nm = fmaxf(m, mo);
            s = s * __expf(m - nm) + so * __expf(mo - nm);
            m = nm;
        }
        if (lr == 0) {
            int row = wm * 32 + (slot >> 1) * 16 + (slot & 1) * 8 + lq;
            sm_m[wn * 128 + row] = m;
            sm_s[wn * 128 + row] = s;
        }
    }
    __syncthreads();
    if (t < 128) {
        float m0 = sm_m[t], m1 = sm_m[128 + t];
        float s0 = sm_s[t], s1 = sm_s[128 + t];
        float nm = fmaxf(m0, m1);
        float s = s0 * __expf(m0 - nm) + s1 * __expf(m1 - nm);
        g_rmax[(bh << 10) + i0 + t] = nm;
        g_rinv[(bh << 10) + i0 + t] = 1.f / s;
    }
}

// ---------------------------------------------------------------------------
// Kernel 2: attn = exp(scores-m)*inv (written), ctx = attn @ V via mma.sync.
// Block: 256 thr (8 warps, 4x2), warp tile 32x32, k accumulated over 1024.
// ---------------------------------------------------------------------------
__global__ void __launch_bounds__(256, 1)
k2_av(const float* __restrict__ scores, const float* __restrict__ vg,
      float* __restrict__ attn, float* __restrict__ ctx)
{
    extern __shared__ char dsm_raw[];
    char* smb = (char*)(((uintptr_t)dsm_raw + 1023) & ~(uintptr_t)1023);

    const int t = threadIdx.x, lane = t & 31, wid = t >> 5;
    const int wm = wid >> 1, wn = wid & 1;
    const int bh = blockIdx.y, i0 = blockIdx.x << 7;

    char* sPH = smb;                 // 128 x 128 bf16 swizzled (32KB)
    char* sPL = smb + 32768;
    char* sVH = smb + 65536;         // 128 x 64 bf16 swizzled (16KB)
    char* sVL = smb + 81920;
    float* smM = (float*)(smb + 98304);
    float* smI = (float*)(smb + 98816);

    const uint32_t uPH = smem_u32(sPH), uPL = smem_u32(sPL);
    const uint32_t uVH = smem_u32(sVH), uVL = smem_u32(sVL);

    if (t < 128) {
        smM[t] = g_rmax[(bh << 10) + i0 + t];
        smI[t] = g_rinv[(bh << 10) + i0 + t];
    }
    __syncthreads();

    float acc[2][4][4];
    #pragma unroll
    for (int mb = 0; mb < 2; ++mb)
        #pragma unroll
        for (int nt = 0; nt < 4; ++nt)
            #pragma unroll
            for (int e = 0; e < 4; ++e) acc[mb][nt][e] = 0.f;

    const int arow = wm * 32 + (lane & 15);
    const int lq = lane >> 2, lr = lane & 3;

    for (int jt = 0; jt < 8; ++jt) {
        const int j0 = jt << 7;
        if (jt) __syncthreads();   // prior mma reads done before overwrite

        // P chunk: scores -> exp -> attn write + bf16 split to smem
        {
            const size_t rb = ((size_t)bh << 20) + (size_t)i0 * NS + j0;
            #pragma unroll
            for (int c = 0; c < 16; ++c) {
                int idx = (c << 8) + t;          // 4096 float4
                int row = idx >> 5, f4 = idx & 31;
                const float4 s = *reinterpret_cast<const float4*>(
                    scores + rb + (size_t)row * NS + (f4 << 2));
                float m = smM[row], inv = smI[row];
                float4 p;
                p.x = __expf(s.x - m) * inv;
                p.y = __expf(s.y - m) * inv;
                p.z = __expf(s.z - m) * inv;
                p.w = __expf(s.w - m) * inv;
                *reinterpret_cast<float4*>(attn + rb + (size_t)row * NS + (f4 << 2)) = p;
                uint32_t h0, l0, h1, l1;
                split2(p.x, p.y, h0, l0);
                split2(p.z, p.w, h1, l1);
                uint32_t o = off128(row, f4 << 2);
                *reinterpret_cast<uint2*>(sPH + o) = make_uint2(h0, h1);
                *reinterpret_cast<uint2*>(sPL + o) = make_uint2(l0, l1);
            }
        }
        load_split64(vg + ((size_t)bh * NS + j0) * DD, sVH, sVL, t);
        __syncthreads();

        #pragma unroll
        for (int ks = 0; ks < 8; ++ks) {
            const int kc = ks * 16 + ((lane >> 4) << 3);
            uint32_t aH[2][4], aL[2][4];
            #pragma unroll
            for (int mb = 0; mb < 2; ++mb) {
                uint32_t o = off128(arow + mb * 16, kc);
                ldsm4(aH[mb], uPH + o);
                ldsm4(aL[mb], uPL + o);
            }
            #pragma unroll
            for (int g = 0; g < 2; ++g) {
                // V trans: rows are k (j index), cols are d
                uint32_t bo = off64(ks * 16 + (lane & 15),
                                    wn * 32 + g * 16 + ((lane >> 4) << 3));
                uint32_t bH[4], bL[4];
                ldsm4t(bH, uVH + bo);
                ldsm4t(bL, uVL + bo);
                #pragma unroll
                for (int mb = 0; mb < 2; ++mb) {
                    // trans pairing: n-first8 -> (r0, r1); n-second8 -> (r2, r3)
                    mma16816(acc[mb][2 * g],     aH[mb], bH[0], bH[1]);
                    mma16816(acc[mb][2 * g + 1], aH[mb], bH[2], bH[3]);
                    mma16816(acc[mb][2 * g],     aH[mb], bL[0], bL[1]);
                    mma16816(acc[mb][2 * g + 1], aH[mb], bL[2], bL[3]);
                    mma16816(acc[mb][2 * g],     aL[mb], bH[0], bH[1]);
                    mma16816(acc[mb][2 * g + 1], aL[mb], bH[2], bH[3]);
                }
            }
        }
    }

    // write context
    #pragma unroll
    for (int mb = 0; mb < 2; ++mb) {
        #pragma unroll
        for (int sl = 0; sl < 2; ++sl) {
            const int grow = i0 + wm * 32 + mb * 16 + sl * 8 + lq;
            float* cp = ctx + (((size_t)bh << 10) + grow) * DD + wn * 32 + lr * 2;
            #pragma unroll
            for (int nt = 0; nt < 4; ++nt) {
                float2 o;
                o.x = acc[mb][nt][sl * 2];
                o.y = acc[mb][nt][sl * 2 + 1];
                *reinterpret_cast<float2*>(cp + nt * 8) = o;
            }
        }
    }
}

// ---------------------------------------------------------------------------
extern "C" void kernel_launch(void* const* d_in, const int* in_sizes, int n_in,
                              void* d_out, int out_size)
{
    const float* q = (const float*)d_in[0];
    const float* k = (const float*)d_in[1];
    const float* v = (const float*)d_in[2];

    float* out    = (float*)d_out;
    float* ctx    = out;                                  // [T,B,H,N,D]
    float* scores = out + (size_t)BHN * NS * DD;          // [T,B,H,N,N]
    float* attn   = scores + (size_t)BHN * NS * NS;       // [T,B,H,N,N]

    cudaFuncSetAttribute(k1_scores, cudaFuncAttributeMaxDynamicSharedMemorySize, K1_SMEM);
    cudaFuncSetAttribute(k2_av,     cudaFuncAttributeMaxDynamicSharedMemorySize, K2_SMEM);

    dim3 g(NS / 128, BHN);
    k1_scores<<<g, 256, K1_SMEM>>>(q, k, scores);
    k2_av<<<g, 256, K2_SMEM>>>(scores, v, attn, ctx);
}

// round 7
// speedup vs baseline: 1.6885x; 1.5335x over previous
#include <cuda_runtime.h>
#include <cuda_bf16.h>
#include <cstdint>
#include <math.h>

#define BHN 64
#define NS  1024
#define DD  64

// softmax row stats (no cudaMalloc allowed -> device globals)
__device__ float g_rmax[BHN * NS];
__device__ float g_rinv[BHN * NS];

// ---------------- helpers ----------------
__device__ __forceinline__ uint32_t smem_u32(const void* p) {
    uint32_t a;
    asm("{ .reg .u64 t; cvta.to.shared.u64 t, %1; cvt.u32.u64 %0, t; }" : "=r"(a) : "l"(p));
    return a;
}
// split two floats into bf16 hi/lo packed pairs
__device__ __forceinline__ void split2(float a, float b, uint32_t& hi, uint32_t& lo) {
    __nv_bfloat16 ha = __float2bfloat16_rn(a), hb = __float2bfloat16_rn(b);
    float ra = a - __bfloat162float(ha);
    float rb = b - __bfloat162float(hb);
    __nv_bfloat162 H; H.x = ha; H.y = hb;
    __nv_bfloat162 L; L.x = __float2bfloat16_rn(ra); L.y = __float2bfloat16_rn(rb);
    hi = *reinterpret_cast<uint32_t*>(&H);
    lo = *reinterpret_cast<uint32_t*>(&L);
}

// 64-half rows (128B), 8 chunks of 16B, XOR-swizzled by row%8
__device__ __forceinline__ uint32_t off64(int row, int halfcol) {
    return (uint32_t)((row << 7) + ((((halfcol >> 3) ^ (row & 7)) << 4) | ((halfcol & 7) << 1)));
}
// 128-half rows (256B), 16 chunks of 16B, XOR-swizzled (low 3 chunk bits)
__device__ __forceinline__ uint32_t off128(int row, int halfcol) {
    return (uint32_t)((row << 8) + ((((halfcol >> 3) ^ (row & 7)) << 4) | ((halfcol & 7) << 1)));
}

__device__ __forceinline__ void ldsm4(uint32_t (&r)[4], uint32_t addr) {
    asm volatile("ldmatrix.sync.aligned.m8n8.x4.shared.b16 {%0,%1,%2,%3}, [%4];"
                 : "=r"(r[0]), "=r"(r[1]), "=r"(r[2]), "=r"(r[3]) : "r"(addr));
}
__device__ __forceinline__ void ldsm4t(uint32_t (&r)[4], uint32_t addr) {
    asm volatile("ldmatrix.sync.aligned.m8n8.x4.trans.shared.b16 {%0,%1,%2,%3}, [%4];"
                 : "=r"(r[0]), "=r"(r[1]), "=r"(r[2]), "=r"(r[3]) : "r"(addr));
}
__device__ __forceinline__ void mma16816(float* c, const uint32_t (&a)[4], uint32_t b0, uint32_t b1) {
    asm volatile(
        "mma.sync.aligned.m16n8k16.row.col.f32.bf16.bf16.f32 "
        "{%0,%1,%2,%3}, {%4,%5,%6,%7}, {%8,%9}, {%0,%1,%2,%3};"
        : "+f"(c[0]), "+f"(c[1]), "+f"(c[2]), "+f"(c[3])
        : "r"(a[0]), "r"(a[1]), "r"(a[2]), "r"(a[3]), "r"(b0), "r"(b1));
}

// load a 128x64 f32 tile, split to bf16 hi/lo, store swizzled (256 threads)
__device__ __forceinline__ void load_split128x64(const float* __restrict__ g,
                                                 char* smH, char* smL, int t) {
    const float4* p = (const float4*)g;
    #pragma unroll
    for (int c = 0; c < 8; ++c) {
        int idx = (c << 8) + t;            // 2048 float4
        float4 x = p[idx];
        int row = idx >> 4, d0 = (idx & 15) << 2;
        uint32_t h0, l0, h1, l1;
        split2(x.x, x.y, h0, l0);
        split2(x.z, x.w, h1, l1);
        uint32_t o = off64(row, d0);
        *reinterpret_cast<uint2*>(smH + o) = make_uint2(h0, h1);
        *reinterpret_cast<uint2*>(smL + o) = make_uint2(l0, l1);
    }
}
// load a 64x64 f32 tile, split, store swizzled (256 threads)
__device__ __forceinline__ void load_split64x64(const float* __restrict__ g,
                                                char* smH, char* smL, int t) {
    const float4* p = (const float4*)g;
    #pragma unroll
    for (int c = 0; c < 4; ++c) {
        int idx = (c << 8) + t;            // 1024 float4
        float4 x = p[idx];
        int row = idx >> 4, d0 = (idx & 15) << 2;
        uint32_t h0, l0, h1, l1;
        split2(x.x, x.y, h0, l0);
        split2(x.z, x.w, h1, l1);
        uint32_t o = off64(row, d0);
        *reinterpret_cast<uint2*>(smH + o) = make_uint2(h0, h1);
        *reinterpret_cast<uint2*>(smL + o) = make_uint2(l0, l1);
    }
}

#define K1_SMEM (49152 + 2048 + 1024)
#define K2_SMEM (65536 + 512 + 1024)

// ---------------------------------------------------------------------------
// Kernel 1: scores = (Q K^T)/8, bf16 3-pass mma.sync; online stats fused.
// Block 256 thr (8 warps: 2 m-groups x 4 n-groups), i-tile 64, j-step 128.
// ---------------------------------------------------------------------------
__global__ void __launch_bounds__(256, 2)
k1_scores(const float* __restrict__ qg, const float* __restrict__ kg,
          float* __restrict__ scores)
{
    extern __shared__ char dsm_raw[];
    char* smb = (char*)(((uintptr_t)dsm_raw + 1023) & ~(uintptr_t)1023);

    const int t = threadIdx.x, lane = t & 31, wid = t >> 5;
    const int wm = wid >> 2, wn = wid & 3;
    const int bh = blockIdx.y, i0 = blockIdx.x << 6;

    char* sQH = smb;                    // 64x64  (8KB)
    char* sQL = smb + 8192;
    char* sKH = smb + 16384;            // 128x64 (16KB)
    char* sKL = smb + 32768;
    float* sm_m = (float*)(smb + 49152);   // [4][64]
    float* sm_s = (float*)(smb + 50176);   // [4][64]

    const uint32_t uQH = smem_u32(sQH), uQL = smem_u32(sQL);
    const uint32_t uKH = smem_u32(sKH), uKL = smem_u32(sKL);

    load_split64x64(qg + ((size_t)bh * NS + i0) * DD, sQH, sQL, t);

    float m_run[4], s_run[4];
    #pragma unroll
    for (int s = 0; s < 4; ++s) { m_run[s] = -INFINITY; s_run[s] = 0.f; }

    const int arow = wm * 32 + (lane & 15);
    const int lq = lane >> 2, lr = lane & 3;

    for (int jt = 0; jt < 8; ++jt) {
        const int j0 = jt << 7;
        load_split128x64(kg + ((size_t)bh * NS + j0) * DD, sKH, sKL, t);
        __syncthreads();

        float acc[2][4][4];
        #pragma unroll
        for (int mb = 0; mb < 2; ++mb)
            #pragma unroll
            for (int nt = 0; nt < 4; ++nt)
                #pragma unroll
                for (int e = 0; e < 4; ++e) acc[mb][nt][e] = 0.f;

        #pragma unroll
        for (int ks = 0; ks < 4; ++ks) {
            const int kc = ks * 16 + ((lane >> 4) << 3);
            uint32_t aH[2][4], aL[2][4];
            #pragma unroll
            for (int mb = 0; mb < 2; ++mb) {
                uint32_t o = off64(arow + mb * 16, kc);
                ldsm4(aH[mb], uQH + o);
                ldsm4(aL[mb], uQL + o);
            }
            #pragma unroll
            for (int g = 0; g < 2; ++g) {
                uint32_t bo = off64(wn * 32 + g * 16 + (lane & 15), kc);
                uint32_t bH[4], bL[4];
                ldsm4(bH, uKH + bo);
                ldsm4(bL, uKL + bo);
                #pragma unroll
                for (int mb = 0; mb < 2; ++mb) {
                    // n-tile 2g : frag (r0, r2); n-tile 2g+1 : frag (r1, r3)
                    mma16816(acc[mb][2 * g],     aH[mb], bH[0], bH[2]);
                    mma16816(acc[mb][2 * g + 1], aH[mb], bH[1], bH[3]);
                    mma16816(acc[mb][2 * g],     aH[mb], bL[0], bL[2]);
                    mma16816(acc[mb][2 * g + 1], aH[mb], bL[1], bL[3]);
                    mma16816(acc[mb][2 * g],     aL[mb], bH[0], bH[2]);
                    mma16816(acc[mb][2 * g + 1], aL[mb], bH[1], bH[3]);
                }
            }
        }

        // epilogue: scale, online stats, write scores
        #pragma unroll
        for (int mb = 0; mb < 2; ++mb) {
            #pragma unroll
            for (int sl = 0; sl < 2; ++sl) {
                float v[8];
                float cm = -INFINITY;
                #pragma unroll
                for (int nt = 0; nt < 4; ++nt) {
                    v[2 * nt]     = acc[mb][nt][sl * 2]     * 0.125f;
                    v[2 * nt + 1] = acc[mb][nt][sl * 2 + 1] * 0.125f;
                    cm = fmaxf(cm, fmaxf(v[2 * nt], v[2 * nt + 1]));
                }
                const int slot = mb * 2 + sl;
                float nm = fmaxf(m_run[slot], cm);
                float a = 0.f;
                #pragma unroll
                for (int e = 0; e < 8; ++e) a += __expf(v[e] - nm);
                s_run[slot] = s_run[slot] * __expf(m_run[slot] - nm) + a;
                m_run[slot] = nm;

                const int grow = i0 + wm * 32 + mb * 16 + sl * 8 + lq;
                float* sp = scores + ((size_t)bh << 20) + (size_t)grow * NS
                            + j0 + wn * 32 + lr * 2;
                #pragma unroll
                for (int nt = 0; nt < 4; ++nt) {
                    float2 o; o.x = v[2 * nt]; o.y = v[2 * nt + 1];
                    *reinterpret_cast<float2*>(sp + nt * 8) = o;
                }
            }
        }
        __syncthreads();
    }

    // lane-quad reduce (m,s), then cross-warp(N) combine over 4 n-groups
    #pragma unroll
    for (int slot = 0; slot < 4; ++slot) {
        float m = m_run[slot], s = s_run[slot];
        #pragma unroll
        for (int o = 1; o <= 2; o <<= 1) {
            float mo = __shfl_xor_sync(0xffffffffu, m, o);
            float so = __shfl_xor_sync(0xffffffffu, s, o);
            float nm = fmaxf(m, mo);
            s = s * __expf(m - nm) + so * __expf(mo - nm);
            m = nm;
        }
        if (lr == 0) {
            int row = wm * 32 + (slot >> 1) * 16 + (slot & 1) * 8 + lq;
            sm_m[wn * 64 + row] = m;
            sm_s[wn * 64 + row] = s;
        }
    }
    __syncthreads();
    if (t < 64) {
        float m = sm_m[t], s = sm_s[t];
        #pragma unroll
        for (int w = 1; w < 4; ++w) {
            float mo = sm_m[w * 64 + t], so = sm_s[w * 64 + t];
            float nm = fmaxf(m, mo);
            s = s * __expf(m - nm) + so * __expf(mo - nm);
            m = nm;
        }
        g_rmax[(bh << 10) + i0 + t] = m;
        g_rinv[(bh << 10) + i0 + t] = 1.f / s;
    }
}

// ---------------------------------------------------------------------------
// Kernel 2: attn = exp(scores-m)*inv (written), ctx = attn @ V, bf16 3-pass.
// Block 256 thr (8 warps: 2 m-groups x 4 n-groups), i-tile 64, j-step 128.
// ---------------------------------------------------------------------------
__global__ void __launch_bounds__(256, 2)
k2_av(const float* __restrict__ scores, const float* __restrict__ vg,
      float* __restrict__ attn, float* __restrict__ ctx)
{
    extern __shared__ char dsm_raw[];
    char* smb = (char*)(((uintptr_t)dsm_raw + 1023) & ~(uintptr_t)1023);

    const int t = threadIdx.x, lane = t & 31, wid = t >> 5;
    const int wm = wid >> 2, wn = wid & 3;
    const int bh = blockIdx.y, i0 = blockIdx.x << 6;

    char* sPH = smb;                 // 64 x 128 bf16 swizzled (16KB)
    char* sPL = smb + 16384;
    char* sVH = smb + 32768;         // 128 x 64 bf16 swizzled (16KB)
    char* sVL = smb + 49152;
    float* smM = (float*)(smb + 65536);
    float* smI = (float*)(smb + 65792);

    const uint32_t uPH = smem_u32(sPH), uPL = smem_u32(sPL);
    const uint32_t uVH = smem_u32(sVH), uVL = smem_u32(sVL);

    if (t < 64) {
        smM[t] = g_rmax[(bh << 10) + i0 + t];
        smI[t] = g_rinv[(bh << 10) + i0 + t];
    }
    __syncthreads();

    float acc[2][2][4];
    #pragma unroll
    for (int mb = 0; mb < 2; ++mb)
        #pragma unroll
        for (int nt = 0; nt < 2; ++nt)
            #pragma unroll
            for (int e = 0; e < 4; ++e) acc[mb][nt][e] = 0.f;

    const int arow = wm * 32 + (lane & 15);
    const int lq = lane >> 2, lr = lane & 3;

    for (int jt = 0; jt < 8; ++jt) {
        const int j0 = jt << 7;
        if (jt) __syncthreads();   // prior mma reads done before overwrite

        // P chunk: scores -> exp -> attn write + bf16 split to smem (64x128)
        {
            const size_t rb = ((size_t)bh << 20) + (size_t)i0 * NS + j0;
            #pragma unroll
            for (int c = 0; c < 8; ++c) {
                int idx = (c << 8) + t;          // 2048 float4
                int row = idx >> 5, f4 = idx & 31;
                const float4 s = *reinterpret_cast<const float4*>(
                    scores + rb + (size_t)row * NS + (f4 << 2));
                float m = smM[row], inv = smI[row];
                float4 p;
                p.x = __expf(s.x - m) * inv;
                p.y = __expf(s.y - m) * inv;
                p.z = __expf(s.z - m) * inv;
                p.w = __expf(s.w - m) * inv;
                *reinterpret_cast<float4*>(attn + rb + (size_t)row * NS + (f4 << 2)) = p;
                uint32_t h0, l0, h1, l1;
                split2(p.x, p.y, h0, l0);
                split2(p.z, p.w, h1, l1);
                uint32_t o = off128(row, f4 << 2);
                *reinterpret_cast<uint2*>(sPH + o) = make_uint2(h0, h1);
                *reinterpret_cast<uint2*>(sPL + o) = make_uint2(l0, l1);
            }
        }
        load_split128x64(vg + ((size_t)bh * NS + j0) * DD, sVH, sVL, t);
        __syncthreads();

        #pragma unroll
        for (int ks = 0; ks < 8; ++ks) {
            const int kc = ks * 16 + ((lane >> 4) << 3);
            uint32_t aH[2][4], aL[2][4];
            #pragma unroll
            for (int mb = 0; mb < 2; ++mb) {
                uint32_t o = off128(arow + mb * 16, kc);
                ldsm4(aH[mb], uPH + o);
                ldsm4(aL[mb], uPL + o);
            }
            // V trans: rows are k (j index), cols are d; warp covers 16 d-cols
            uint32_t bo = off64(ks * 16 + (lane & 15),
                                wn * 16 + ((lane >> 4) << 3));
            uint32_t bH[4], bL[4];
            ldsm4t(bH, uVH + bo);
            ldsm4t(bL, uVL + bo);
            #pragma unroll
            for (int mb = 0; mb < 2; ++mb) {
                // trans pairing: n-first8 -> (r0, r1); n-second8 -> (r2, r3)
                mma16816(acc[mb][0], aH[mb], bH[0], bH[1]);
                mma16816(acc[mb][1], aH[mb], bH[2], bH[3]);
                mma16816(acc[mb][0], aH[mb], bL[0], bL[1]);
                mma16816(acc[mb][1], aH[mb], bL[2], bL[3]);
                mma16816(acc[mb][0], aL[mb], bH[0], bH[1]);
                mma16816(acc[mb][1], aL[mb], bH[2], bH[3]);
            }
        }
    }

    // write context
    #pragma unroll
    for (int mb = 0; mb < 2; ++mb) {
        #pragma unroll
        for (int sl = 0; sl < 2; ++sl) {
            const int grow = i0 + wm * 32 + mb * 16 + sl * 8 + lq;
            float* cp = ctx + (((size_t)bh << 10) + grow) * DD + wn * 16 + lr * 2;
            #pragma unroll
            for (int nt = 0; nt < 2; ++nt) {
                float2 o;
                o.x = acc[mb][nt][sl * 2];
                o.y = acc[mb][nt][sl * 2 + 1];
                *reinterpret_cast<float2*>(cp + nt * 8) = o;
            }
        }
    }
}

// ---------------------------------------------------------------------------
extern "C" void kernel_launch(void* const* d_in, const int* in_sizes, int n_in,
                              void* d_out, int out_size)
{
    const float* q = (const float*)d_in[0];
    const float* k = (const float*)d_in[1];
    const float* v = (const float*)d_in[2];

    float* out    = (float*)d_out;
    float* ctx    = out;                                  // [T,B,H,N,D]
    float* scores = out + (size_t)BHN * NS * DD;          // [T,B,H,N,N]
    float* attn   = scores + (size_t)BHN * NS * NS;       // [T,B,H,N,N]

    cudaFuncSetAttribute(k1_scores, cudaFuncAttributeMaxDynamicSharedMemorySize, K1_SMEM);
    cudaFuncSetAttribute(k2_av,     cudaFuncAttributeMaxDynamicSharedMemorySize, K2_SMEM);

    dim3 g(NS / 64, BHN);
    k1_scores<<<g, 256, K1_SMEM>>>(q, k, scores);
    k2_av<<<g, 256, K2_SMEM>>>(scores, v, attn, ctx);
}

// round 8
// speedup vs baseline: 1.8087x; 1.0712x over previous
#include <cuda_runtime.h>
#include <cuda_bf16.h>
#include <cstdint>
#include <math.h>

#define BHN 64
#define NS  1024
#define DD  64

// softmax row stats (no cudaMalloc allowed -> device globals)
__device__ float g_rmax[BHN * NS];
__device__ float g_rinv[BHN * NS];

// ---------------- helpers ----------------
__device__ __forceinline__ uint32_t smem_u32(const void* p) {
    uint32_t a;
    asm("{ .reg .u64 t; cvta.to.shared.u64 t, %1; cvt.u32.u64 %0, t; }" : "=r"(a) : "l"(p));
    return a;
}
// split two floats into bf16 hi/lo packed pairs
__device__ __forceinline__ void split2(float a, float b, uint32_t& hi, uint32_t& lo) {
    __nv_bfloat16 ha = __float2bfloat16_rn(a), hb = __float2bfloat16_rn(b);
    float ra = a - __bfloat162float(ha);
    float rb = b - __bfloat162float(hb);
    __nv_bfloat162 H; H.x = ha; H.y = hb;
    __nv_bfloat162 L; L.x = __float2bfloat16_rn(ra); L.y = __float2bfloat16_rn(rb);
    hi = *reinterpret_cast<uint32_t*>(&H);
    lo = *reinterpret_cast<uint32_t*>(&L);
}

// 64-half rows (128B), 8 chunks of 16B, XOR-swizzled by row%8
__device__ __forceinline__ uint32_t off64(int row, int halfcol) {
    return (uint32_t)((row << 7) + ((((halfcol >> 3) ^ (row & 7)) << 4) | ((halfcol & 7) << 1)));
}

__device__ __forceinline__ void ldsm4(uint32_t (&r)[4], uint32_t addr) {
    asm volatile("ldmatrix.sync.aligned.m8n8.x4.shared.b16 {%0,%1,%2,%3}, [%4];"
                 : "=r"(r[0]), "=r"(r[1]), "=r"(r[2]), "=r"(r[3]) : "r"(addr));
}
__device__ __forceinline__ void ldsm4t(uint32_t (&r)[4], uint32_t addr) {
    asm volatile("ldmatrix.sync.aligned.m8n8.x4.trans.shared.b16 {%0,%1,%2,%3}, [%4];"
                 : "=r"(r[0]), "=r"(r[1]), "=r"(r[2]), "=r"(r[3]) : "r"(addr));
}
__device__ __forceinline__ void mma16816(float* c, const uint32_t (&a)[4], uint32_t b0, uint32_t b1) {
    asm volatile(
        "mma.sync.aligned.m16n8k16.row.col.f32.bf16.bf16.f32 "
        "{%0,%1,%2,%3}, {%4,%5,%6,%7}, {%8,%9}, {%0,%1,%2,%3};"
        : "+f"(c[0]), "+f"(c[1]), "+f"(c[2]), "+f"(c[3])
        : "r"(a[0]), "r"(a[1]), "r"(a[2]), "r"(a[3]), "r"(b0), "r"(b1));
}

// load a 64x64 f32 tile, split to bf16 hi/lo, store swizzled (256 threads)
__device__ __forceinline__ void load_split64x64(const float* __restrict__ g,
                                                char* smH, char* smL, int t) {
    const float4* p = (const float4*)g;
    #pragma unroll
    for (int c = 0; c < 4; ++c) {
        int idx = (c << 8) + t;            // 1024 float4
        float4 x = p[idx];
        int row = idx >> 4, d0 = (idx & 15) << 2;
        uint32_t h0, l0, h1, l1;
        split2(x.x, x.y, h0, l0);
        split2(x.z, x.w, h1, l1);
        uint32_t o = off64(row, d0);
        *reinterpret_cast<uint2*>(smH + o) = make_uint2(h0, h1);
        *reinterpret_cast<uint2*>(smL + o) = make_uint2(l0, l1);
    }
}

#define K1_SMEM (32768 + 2048 + 1024)
#define K2_SMEM (32768 + 512 + 1024)

// ---------------------------------------------------------------------------
// Kernel 1: scores = (Q K^T)/8, bf16 3-pass mma.sync; online stats fused.
// Block 256 thr (8 warps: 2 m-groups x 4 n-groups), i-tile 64, j-step 64.
// ---------------------------------------------------------------------------
__global__ void __launch_bounds__(256, 3)
k1_scores(const float* __restrict__ qg, const float* __restrict__ kg,
          float* __restrict__ scores)
{
    extern __shared__ char dsm_raw[];
    char* smb = (char*)(((uintptr_t)dsm_raw + 1023) & ~(uintptr_t)1023);

    const int t = threadIdx.x, lane = t & 31, wid = t >> 5;
    const int wm = wid >> 2, wn = wid & 3;
    const int bh = blockIdx.y, i0 = blockIdx.x << 6;

    char* sQH = smb;                    // 64x64 bf16 (8KB)
    char* sQL = smb + 8192;
    char* sKH = smb + 16384;            // 64x64 bf16 (8KB)
    char* sKL = smb + 24576;
    float* sm_m = (float*)(smb + 32768);   // [4][64]
    float* sm_s = (float*)(smb + 33792);   // [4][64]

    const uint32_t uQH = smem_u32(sQH), uQL = smem_u32(sQL);
    const uint32_t uKH = smem_u32(sKH), uKL = smem_u32(sKL);

    load_split64x64(qg + ((size_t)bh * NS + i0) * DD, sQH, sQL, t);

    float m_run[4], s_run[4];
    #pragma unroll
    for (int s = 0; s < 4; ++s) { m_run[s] = -INFINITY; s_run[s] = 0.f; }

    const int arow = wm * 32 + (lane & 15);
    const int lq = lane >> 2, lr = lane & 3;

    for (int jt = 0; jt < 16; ++jt) {
        const int j0 = jt << 6;
        load_split64x64(kg + ((size_t)bh * NS + j0) * DD, sKH, sKL, t);
        __syncthreads();

        float acc[2][2][4];
        #pragma unroll
        for (int mb = 0; mb < 2; ++mb)
            #pragma unroll
            for (int nt = 0; nt < 2; ++nt)
                #pragma unroll
                for (int e = 0; e < 4; ++e) acc[mb][nt][e] = 0.f;

        #pragma unroll
        for (int ks = 0; ks < 4; ++ks) {
            const int kc = ks * 16 + ((lane >> 4) << 3);
            uint32_t aH[2][4], aL[2][4];
            #pragma unroll
            for (int mb = 0; mb < 2; ++mb) {
                uint32_t o = off64(arow + mb * 16, kc);
                ldsm4(aH[mb], uQH + o);
                ldsm4(aL[mb], uQL + o);
            }
            uint32_t bo = off64(wn * 16 + (lane & 15), kc);
            uint32_t bH[4], bL[4];
            ldsm4(bH, uKH + bo);
            ldsm4(bL, uKL + bo);
            #pragma unroll
            for (int mb = 0; mb < 2; ++mb) {
                // n-tile 0 : frag (r0, r2); n-tile 1 : frag (r1, r3)
                mma16816(acc[mb][0], aH[mb], bH[0], bH[2]);
                mma16816(acc[mb][1], aH[mb], bH[1], bH[3]);
                mma16816(acc[mb][0], aH[mb], bL[0], bL[2]);
                mma16816(acc[mb][1], aH[mb], bL[1], bL[3]);
                mma16816(acc[mb][0], aL[mb], bH[0], bH[2]);
                mma16816(acc[mb][1], aL[mb], bH[1], bH[3]);
            }
        }

        // epilogue: scale, online stats, write scores
        #pragma unroll
        for (int mb = 0; mb < 2; ++mb) {
            #pragma unroll
            for (int sl = 0; sl < 2; ++sl) {
                float v[4];
                float cm = -INFINITY;
                #pragma unroll
                for (int nt = 0; nt < 2; ++nt) {
                    v[2 * nt]     = acc[mb][nt][sl * 2]     * 0.125f;
                    v[2 * nt + 1] = acc[mb][nt][sl * 2 + 1] * 0.125f;
                    cm = fmaxf(cm, fmaxf(v[2 * nt], v[2 * nt + 1]));
                }
                const int slot = mb * 2 + sl;
                float nm = fmaxf(m_run[slot], cm);
                float a = 0.f;
                #pragma unroll
                for (int e = 0; e < 4; ++e) a += __expf(v[e] - nm);
                s_run[slot] = s_run[slot] * __expf(m_run[slot] - nm) + a;
                m_run[slot] = nm;

                const int grow = i0 + wm * 32 + mb * 16 + sl * 8 + lq;
                float* sp = scores + ((size_t)bh << 20) + (size_t)grow * NS
                            + j0 + wn * 16 + lr * 2;
                #pragma unroll
                for (int nt = 0; nt < 2; ++nt) {
                    float2 o; o.x = v[2 * nt]; o.y = v[2 * nt + 1];
                    *reinterpret_cast<float2*>(sp + nt * 8) = o;
                }
            }
        }
        __syncthreads();
    }

    // lane-quad reduce (m,s), then cross-warp(N) combine over 4 n-groups
    #pragma unroll
    for (int slot = 0; slot < 4; ++slot) {
        float m = m_run[slot], s = s_run[slot];
        #pragma unroll
        for (int o = 1; o <= 2; o <<= 1) {
            float mo = __shfl_xor_sync(0xffffffffu, m, o);
            float so = __shfl_xor_sync(0xffffffffu, s, o);
            float nm = fmaxf(m, mo);
            s = s * __expf(m - nm) + so * __expf(mo - nm);
            m = nm;
        }
        if (lr == 0) {
            int row = wm * 32 + (slot >> 1) * 16 + (slot & 1) * 8 + lq;
            sm_m[wn * 64 + row] = m;
            sm_s[wn * 64 + row] = s;
        }
    }
    __syncthreads();
    if (t < 64) {
        float m = sm_m[t], s = sm_s[t];
        #pragma unroll
        for (int w = 1; w < 4; ++w) {
            float mo = sm_m[w * 64 + t], so = sm_s[w * 64 + t];
            float nm = fmaxf(m, mo);
            s = s * __expf(m - nm) + so * __expf(mo - nm);
            m = nm;
        }
        g_rmax[(bh << 10) + i0 + t] = m;
        g_rinv[(bh << 10) + i0 + t] = 1.f / s;
    }
}

// ---------------------------------------------------------------------------
// Kernel 2: attn = exp(scores-m)*inv (written), ctx = attn @ V, bf16 3-pass.
// Block 256 thr (8 warps: 2 m-groups x 4 n-groups), i-tile 64, j-step 64.
// ---------------------------------------------------------------------------
__global__ void __launch_bounds__(256, 3)
k2_av(const float* __restrict__ scores, const float* __restrict__ vg,
      float* __restrict__ attn, float* __restrict__ ctx)
{
    extern __shared__ char dsm_raw[];
    char* smb = (char*)(((uintptr_t)dsm_raw + 1023) & ~(uintptr_t)1023);

    const int t = threadIdx.x, lane = t & 31, wid = t >> 5;
    const int wm = wid >> 2, wn = wid & 3;
    const int bh = blockIdx.y, i0 = blockIdx.x << 6;

    char* sPH = smb;                 // 64 x 64 bf16 swizzled (8KB)
    char* sPL = smb + 8192;
    char* sVH = smb + 16384;         // 64 x 64 bf16 swizzled (8KB)
    char* sVL = smb + 24576;
    float* smM = (float*)(smb + 32768);
    float* smI = (float*)(smb + 33024);

    const uint32_t uPH = smem_u32(sPH), uPL = smem_u32(sPL);
    const uint32_t uVH = smem_u32(sVH), uVL = smem_u32(sVL);

    if (t < 64) {
        smM[t] = g_rmax[(bh << 10) + i0 + t];
        smI[t] = g_rinv[(bh << 10) + i0 + t];
    }
    __syncthreads();

    float acc[2][2][4];
    #pragma unroll
    for (int mb = 0; mb < 2; ++mb)
        #pragma unroll
        for (int nt = 0; nt < 2; ++nt)
            #pragma unroll
            for (int e = 0; e < 4; ++e) acc[mb][nt][e] = 0.f;

    const int arow = wm * 32 + (lane & 15);
    const int lq = lane >> 2, lr = lane & 3;

    for (int jt = 0; jt < 16; ++jt) {
        const int j0 = jt << 6;
        if (jt) __syncthreads();   // prior mma reads done before overwrite

        // P chunk: scores -> exp -> attn write + bf16 split to smem (64x64)
        {
            const size_t rb = ((size_t)bh << 20) + (size_t)i0 * NS + j0;
            #pragma unroll
            for (int c = 0; c < 4; ++c) {
                int idx = (c << 8) + t;          // 1024 float4
                int row = idx >> 4, f4 = idx & 15;
                const float4 s = *reinterpret_cast<const float4*>(
                    scores + rb + (size_t)row * NS + (f4 << 2));
                float m = smM[row], inv = smI[row];
                float4 p;
                p.x = __expf(s.x - m) * inv;
                p.y = __expf(s.y - m) * inv;
                p.z = __expf(s.z - m) * inv;
                p.w = __expf(s.w - m) * inv;
                *reinterpret_cast<float4*>(attn + rb + (size_t)row * NS + (f4 << 2)) = p;
                uint32_t h0, l0, h1, l1;
                split2(p.x, p.y, h0, l0);
                split2(p.z, p.w, h1, l1);
                uint32_t o = off64(row, f4 << 2);
                *reinterpret_cast<uint2*>(sPH + o) = make_uint2(h0, h1);
                *reinterpret_cast<uint2*>(sPL + o) = make_uint2(l0, l1);
            }
        }
        load_split64x64(vg + ((size_t)bh * NS + j0) * DD, sVH, sVL, t);
        __syncthreads();

        #pragma unroll
        for (int ks = 0; ks < 4; ++ks) {
            const int kc = ks * 16 + ((lane >> 4) << 3);
            uint32_t aH[2][4], aL[2][4];
            #pragma unroll
            for (int mb = 0; mb < 2; ++mb) {
                uint32_t o = off64(arow + mb * 16, kc);
                ldsm4(aH[mb], uPH + o);
                ldsm4(aL[mb], uPL + o);
            }
            // V trans: rows are k (j index), cols are d; warp covers 16 d-cols
            uint32_t bo = off64(ks * 16 + (lane & 15),
                                wn * 16 + ((lane >> 4) << 3));
            uint32_t bH[4], bL[4];
            ldsm4t(bH, uVH + bo);
            ldsm4t(bL, uVL + bo);
            #pragma unroll
            for (int mb = 0; mb < 2; ++mb) {
                // trans pairing: n-first8 -> (r0, r1); n-second8 -> (r2, r3)
                mma16816(acc[mb][0], aH[mb], bH[0], bH[1]);
                mma16816(acc[mb][1], aH[mb], bH[2], bH[3]);
                mma16816(acc[mb][0], aH[mb], bL[0], bL[1]);
                mma16816(acc[mb][1], aH[mb], bL[2], bL[3]);
                mma16816(acc[mb][0], aL[mb], bH[0], bH[1]);
                mma16816(acc[mb][1], aL[mb], bH[2], bH[3]);
            }
        }
    }

    // write context
    #pragma unroll
    for (int mb = 0; mb < 2; ++mb) {
        #pragma unroll
        for (int sl = 0; sl < 2; ++sl) {
            const int grow = i0 + wm * 32 + mb * 16 + sl * 8 + lq;
            float* cp = ctx + (((size_t)bh << 10) + grow) * DD + wn * 16 + lr * 2;
            #pragma unroll
            for (int nt = 0; nt < 2; ++nt) {
                float2 o;
                o.x = acc[mb][nt][sl * 2];
                o.y = acc[mb][nt][sl * 2 + 1];
                *reinterpret_cast<float2*>(cp + nt * 8) = o;
            }
        }
    }
}

// ---------------------------------------------------------------------------
extern "C" void kernel_launch(void* const* d_in, const int* in_sizes, int n_in,
                              void* d_out, int out_size)
{
    const float* q = (const float*)d_in[0];
    const float* k = (const float*)d_in[1];
    const float* v = (const float*)d_in[2];

    float* out    = (float*)d_out;
    float* ctx    = out;                                  // [T,B,H,N,D]
    float* scores = out + (size_t)BHN * NS * DD;          // [T,B,H,N,N]
    float* attn   = scores + (size_t)BHN * NS * NS;       // [T,B,H,N,N]

    cudaFuncSetAttribute(k1_scores, cudaFuncAttributeMaxDynamicSharedMemorySize, K1_SMEM);
    cudaFuncSetAttribute(k2_av,     cudaFuncAttributeMaxDynamicSharedMemorySize, K2_SMEM);

    dim3 g(NS / 64, BHN);
    k1_scores<<<g, 256, K1_SMEM>>>(q, k, scores);
    k2_av<<<g, 256, K2_SMEM>>>(scores, v, attn, ctx);
}